// round 5
// baseline (speedup 1.0000x reference)
#include <cuda_runtime.h>
#include <cstdint>

// Problem constants
#define DD   256
#define HW   4096
#define NN   32768
#define KK   8192
#define NTILES 64          // K tiles of 128 codes
#define EPS  2e-3f

// Scratch (no cudaMalloc allowed)
__device__ __align__(16) float g_A[(size_t)NN * DD];   // transposed pixels [n][d], 32 MB
__device__ __align__(16) float g_cbsq[KK];
__device__ float g_xsq[NN];
__device__ float g_pv[NTILES * NN];      // per-(ktile,pixel) min of tc-dist

#define OFF_ZQ1 ((size_t)0)
#define OFF_ZQ2 ((size_t)NN * DD)
#define OFF_LOG ((size_t)2 * NN * DD)

#define SMEM_BYTES (65536 + 1024)   // 2 stages x (A 16KB + B 16KB) + reduce scratch

// ---------------- helpers ----------------
__device__ __forceinline__ uint32_t smem_u32(const void* p) {
    uint32_t a;
    asm("{ .reg .u64 t; cvta.to.shared.u64 t, %1; cvt.u32.u64 %0, t; }" : "=r"(a) : "l"(p));
    return a;
}
__device__ __forceinline__ void cp16(uint32_t dst, const float* src) {
    asm volatile("cp.async.cg.shared.global [%0], [%1], 16;" :: "r"(dst), "l"(src));
}
#define CP_COMMIT() asm volatile("cp.async.commit_group;")
#define CP_WAIT1()  asm volatile("cp.async.wait_group 1;")
#define CP_WAIT0()  asm volatile("cp.async.wait_group 0;")

// tf32 mma: D = A(16x8 row) * B(8x8 col) + D
__device__ __forceinline__ void mma_tf32(float* c, const uint32_t* a, const uint32_t* b) {
    asm volatile(
        "mma.sync.aligned.m16n8k8.row.col.f32.tf32.tf32.f32 "
        "{%0,%1,%2,%3}, {%4,%5,%6,%7}, {%8,%9}, {%0,%1,%2,%3};"
        : "+f"(c[0]), "+f"(c[1]), "+f"(c[2]), "+f"(c[3])
        : "r"(a[0]), "r"(a[1]), "r"(a[2]), "r"(a[3]), "r"(b[0]), "r"(b[1]));
}

// swizzled float index inside a [rows][32-float] tile (conflict-free fragments)
__device__ __forceinline__ int swi(int row, int col) {
    return row * 32 + (((col >> 2) ^ (row & 7)) << 2) + (col & 3);
}
// swizzled float index inside the [128 px][128 col] staging buffer
__device__ __forceinline__ int stg_idx(int px, int col) {
    return px * 128 + (((col >> 2) ^ (px & 7)) << 2) + (col & 3);
}

// ---------------- prep kernels ----------------

// Transpose z [B,D,H,W] -> g_A [n][d] row-major
__global__ void vq_prep(const float* __restrict__ z) {
    __shared__ float s[64 * 257];
    int t = threadIdx.x;
    int n0 = blockIdx.x * 64;
    int b = n0 >> 12, hw0 = n0 & 4095;
    const float* zb = z + (size_t)b * DD * HW + hw0;
#pragma unroll 8
    for (int i = 0; i < 64; i++) {
        int idx = i * 256 + t;
        int d = idx >> 6, px = idx & 63;
        s[px * 257 + d] = zb[(size_t)d * HW + px];
    }
    __syncthreads();
    float* ga = g_A + (size_t)n0 * DD;
#pragma unroll 8
    for (int i = 0; i < 64; i++) {
        ga[(size_t)i * DD + t] = s[i * 257 + t];
    }
}

__global__ void vq_xsq(const float* __restrict__ z) {
    int n = blockIdx.x * 256 + threadIdx.x;
    int b = n >> 12, hw = n & 4095;
    const float* p = z + (size_t)b * DD * HW + hw;
    float s = 0.f;
#pragma unroll 8
    for (int d = 0; d < DD; d++) {
        float v = p[(size_t)d * HW];
        s = fmaf(v, v, s);
    }
    g_xsq[n] = s;
}

__global__ void vq_cbsq(const float* __restrict__ cb) {
    int k = blockIdx.x * 256 + threadIdx.x;
    const float4* r = (const float4*)(cb + (size_t)k * DD);
    float s = 0.f;
#pragma unroll 8
    for (int i = 0; i < DD / 4; i++) {
        float4 v = r[i];
        s = fmaf(v.x, v.x, s); s = fmaf(v.y, v.y, s);
        s = fmaf(v.z, v.z, s); s = fmaf(v.w, v.w, s);
    }
    g_cbsq[k] = s;
}

// ---------------- tf32 mma.sync GEMM + logits + tile-min ----------------
// grid (256 m-tiles, 64 n-tiles), 256 threads (8 warps: 2 m x 4 n), 2 CTAs/SM
__global__ void __launch_bounds__(256, 2)
vq_gemm(const float* __restrict__ cb, float* __restrict__ out) {
    extern __shared__ float sm[];
    const int tid = threadIdx.x, lane = tid & 31, wid = tid >> 5;
    const int wm = wid & 1, wn = wid >> 1;
    const int mtile = blockIdx.x, ntile = blockIdx.y;
    const int n0 = mtile * 128, k0 = ntile * 128;
    const int b = n0 >> 12, hw0 = n0 & 4095;
    const uint32_t sb = smem_u32(sm);

    auto issue = [&](int c) {
        uint32_t base = sb + (uint32_t)(c & 1) * 32768u;
        int coff = c * 32;
#pragma unroll
        for (int i = 0; i < 4; i++) {       // A: 1024 16B chunks
            int ci = tid + i * 256;
            int row = ci >> 3, c4 = ci & 7;
            cp16(base + row * 128 + ((c4 ^ (row & 7)) << 4),
                 g_A + (size_t)(n0 + row) * DD + coff + c4 * 4);
        }
#pragma unroll
        for (int i = 0; i < 4; i++) {       // B: 1024 16B chunks
            int ci = tid + i * 256;
            int row = ci >> 3, c4 = ci & 7;
            cp16(base + 16384 + row * 128 + ((c4 ^ (row & 7)) << 4),
                 cb + (size_t)(k0 + row) * DD + coff + c4 * 4);
        }
        CP_COMMIT();
    };

    float acc[4][4][4];
#pragma unroll
    for (int i = 0; i < 4; i++)
#pragma unroll
        for (int j = 0; j < 4; j++)
#pragma unroll
            for (int r = 0; r < 4; r++) acc[i][j][r] = 0.f;

    issue(0);
    issue(1);

    for (int c = 0; c < 8; c++) {
        if (c < 7) { CP_WAIT1(); } else { CP_WAIT0(); }
        __syncthreads();
        const float* As = sm + (c & 1) * 8192;
        const float* Bs = As + 4096;
#pragma unroll
        for (int kk = 0; kk < 4; kk++) {
            int c0 = kk * 8 + (lane & 3);
            uint32_t af[4][4], bf[4][2];
#pragma unroll
            for (int i = 0; i < 4; i++) {
                int r0 = wm * 64 + i * 16 + (lane >> 2);
                af[i][0] = __float_as_uint(As[swi(r0,     c0)]);
                af[i][1] = __float_as_uint(As[swi(r0 + 8, c0)]);
                af[i][2] = __float_as_uint(As[swi(r0,     c0 + 4)]);
                af[i][3] = __float_as_uint(As[swi(r0 + 8, c0 + 4)]);
            }
#pragma unroll
            for (int j = 0; j < 4; j++) {
                int rb = wn * 32 + j * 8 + (lane >> 2);
                bf[j][0] = __float_as_uint(Bs[swi(rb, c0)]);
                bf[j][1] = __float_as_uint(Bs[swi(rb, c0 + 4)]);
            }
#pragma unroll
            for (int i = 0; i < 4; i++)
#pragma unroll
                for (int j = 0; j < 4; j++)
                    mma_tf32(acc[i][j], af[i], bf[j]);
        }
        __syncthreads();
        if (c + 2 < 8) issue(c + 2);
    }

    // phase 1: dump accumulators into smem staging [128 px][128 col] (swizzled)
#pragma unroll
    for (int i = 0; i < 4; i++) {
#pragma unroll
        for (int j = 0; j < 4; j++) {
            int px = wm * 64 + i * 16 + (lane >> 2);
            int col = wn * 32 + j * 8 + 2 * (lane & 3);
            *(float2*)&sm[stg_idx(px,     col)] = make_float2(acc[i][j][0], acc[i][j][1]);
            *(float2*)&sm[stg_idx(px + 8, col)] = make_float2(acc[i][j][2], acc[i][j][3]);
        }
    }
    __syncthreads();

    // phase 2: dist + coalesced logit stores + per-pixel min
    const int px = tid & 127, half = tid >> 7;
    const float xsv = g_xsq[n0 + px];
    float* lb = out + OFF_LOG + ((size_t)b * KK + k0) * HW + hw0 + px;
    float mn = __int_as_float(0x7f800000);
#pragma unroll
    for (int it = 0; it < 16; it++) {
        int cg = half * 16 + it;        // float4 group of codes (0..31)
        float4 dv = *(const float4*)&sm[px * 128 + ((cg ^ (px & 7)) << 2)];
        float4 cq = *(const float4*)&g_cbsq[k0 + cg * 4];
        float d0 = fmaf(-2.f, dv.x, cq.x + xsv);
        float d1 = fmaf(-2.f, dv.y, cq.y + xsv);
        float d2 = fmaf(-2.f, dv.z, cq.z + xsv);
        float d3 = fmaf(-2.f, dv.w, cq.w + xsv);
        mn = fminf(mn, fminf(fminf(d0, d1), fminf(d2, d3)));
        __stcs(lb + (size_t)(cg * 4 + 0) * HW, -d0);
        __stcs(lb + (size_t)(cg * 4 + 1) * HW, -d1);
        __stcs(lb + (size_t)(cg * 4 + 2) * HW, -d2);
        __stcs(lb + (size_t)(cg * 4 + 3) * HW, -d3);
    }
    float* rv = sm + 16384;
    rv[tid] = mn;
    __syncthreads();
    if (tid < 128)
        g_pv[(size_t)ntile * NN + n0 + tid] = fminf(rv[tid], rv[tid + 128]);
}

// ---------------- candidate rescore (exact fp32) + gather ----------------
// grid 128 blocks x 256 threads; block owns 256 pixels
__global__ void __launch_bounds__(256)
vq_rescore(const float* __restrict__ cb, float* __restrict__ out) {
    __shared__ float sl[32 * 256];     // 32 codes x 256 pixels
    const int t = threadIdx.x;
    const int n0 = blockIdx.x * 256;
    const int n = n0 + t;
    const int b = n >> 12, hw0 = n0 & 4095;

    // global tc-min over tiles
    float m = __int_as_float(0x7f800000);
#pragma unroll 8
    for (int s = 0; s < NTILES; s++) m = fminf(m, g_pv[(size_t)s * NN + n]);
    const float thresh = m + EPS;

    const float xsv = g_xsq[n];
    const float4* xa = (const float4*)(g_A + (size_t)n * DD);
    float bestv = __int_as_float(0x7f800000);
    int bestk = 0;

    const float* lbase = out + OFF_LOG + (size_t)b * KK * HW + hw0;

    for (int kc = 0; kc < KK / 32; kc++) {
        __syncthreads();
#pragma unroll
        for (int i = 0; i < 32; i++)
            sl[i * 256 + t] = __ldcs(lbase + (size_t)(kc * 32 + i) * HW + t);
        __syncthreads();
#pragma unroll 4
        for (int j = 0; j < 32; j++) {
            float dist = -sl[j * 256 + t];
            if (dist <= thresh) {
                int k = kc * 32 + j;
                const float4* cbv = (const float4*)(cb + (size_t)k * DD);
                float s2 = 0.f;
#pragma unroll 8
                for (int q = 0; q < DD / 4; q++) {
                    float4 a = xa[q]; float4 v = cbv[q];
                    s2 = fmaf(a.x, v.x, s2); s2 = fmaf(a.y, v.y, s2);
                    s2 = fmaf(a.z, v.z, s2); s2 = fmaf(a.w, v.w, s2);
                }
                float de = fmaf(-2.f, s2, g_cbsq[k] + xsv);
                if (de < bestv) { bestv = de; bestk = k; }   // ascending k: ties keep lowest
            }
        }
    }

    // gather z_q for the winning code (coalesced across block per d)
    const float4* crow = (const float4*)(cb + (size_t)bestk * DD);
    size_t ob = (size_t)b * DD * HW + hw0 + t;
#pragma unroll 8
    for (int q = 0; q < DD / 4; q++) {
        float4 v = crow[q];
        int d = q * 4;
        out[OFF_ZQ1 + ob + (size_t)(d + 0) * HW] = v.x;
        out[OFF_ZQ1 + ob + (size_t)(d + 1) * HW] = v.y;
        out[OFF_ZQ1 + ob + (size_t)(d + 2) * HW] = v.z;
        out[OFF_ZQ1 + ob + (size_t)(d + 3) * HW] = v.w;
        out[OFF_ZQ2 + ob + (size_t)(d + 0) * HW] = v.x;
        out[OFF_ZQ2 + ob + (size_t)(d + 1) * HW] = v.y;
        out[OFF_ZQ2 + ob + (size_t)(d + 2) * HW] = v.z;
        out[OFF_ZQ2 + ob + (size_t)(d + 3) * HW] = v.w;
    }
}

extern "C" void kernel_launch(void* const* d_in, const int* in_sizes, int n_in,
                              void* d_out, int out_size) {
    const float* z  = (const float*)d_in[0];
    const float* cb = (const float*)d_in[1];
    float* out = (float*)d_out;

    cudaFuncSetAttribute(vq_gemm, cudaFuncAttributeMaxDynamicSharedMemorySize, SMEM_BYTES);

    vq_prep<<<NN / 64, 256>>>(z);
    vq_xsq<<<NN / 256, 256>>>(z);
    vq_cbsq<<<KK / 256, 256>>>(cb);
    vq_gemm<<<dim3(256, NTILES), 256, SMEM_BYTES>>>(cb, out);
    vq_rescore<<<NN / 256, 256>>>(cb, out);
}

// round 7
// speedup vs baseline: 7.1109x; 7.1109x over previous
#include <cuda_runtime.h>
#include <cstdint>

// Problem constants
#define DD   256
#define HW   4096
#define NN   32768
#define KK   8192
#define NTILES 64          // K tiles of 128 codes
#define EPS  2.5e-4f

// Scratch (no cudaMalloc allowed)
__device__ __align__(16) float g_A[(size_t)NN * DD];   // fragment-packed A (32 MB)
__device__ __align__(16) float g_B[(size_t)KK * DD];   // fragment-packed B (8 MB)
__device__ __align__(16) float g_X[(size_t)NN * DD];   // row-major pixels (32 MB)
__device__ __align__(16) float g_cbsq[KK];
__device__ float g_xsq[NN];
__device__ float g_pv[NTILES * NN];      // per-(tile,pixel) tc-min
__device__ int   g_pk[NTILES * NN];      // per-(tile,pixel) tc-argmin
__device__ float g_p2[NTILES * NN];      // per-(tile,pixel) tc-second-min

#define OFF_ZQ1 ((size_t)0)
#define OFF_ZQ2 ((size_t)NN * DD)
#define OFF_LOG ((size_t)2 * NN * DD)

#define SMEM_BYTES 98304    // 3 stages x 32KB (epilogue reuses: 64KB staging + 3KB reduce)

// ---------------- helpers ----------------
__device__ __forceinline__ uint32_t smem_u32(const void* p) {
    uint32_t a;
    asm("{ .reg .u64 t; cvta.to.shared.u64 t, %1; cvt.u32.u64 %0, t; }" : "=r"(a) : "l"(p));
    return a;
}
__device__ __forceinline__ void cp16(uint32_t dst, const float* src) {
    asm volatile("cp.async.cg.shared.global [%0], [%1], 16;" :: "r"(dst), "l"(src));
}
#define CP_COMMIT() asm volatile("cp.async.commit_group;")
#define CP_WAIT2()  asm volatile("cp.async.wait_group 2;")
#define CP_WAIT1()  asm volatile("cp.async.wait_group 1;")
#define CP_WAIT0()  asm volatile("cp.async.wait_group 0;")

// tf32 mma: D = A(16x8 row) * B(8x8 col) + D
__device__ __forceinline__ void mma_tf32(float* c, const uint32_t* a, const uint32_t* b) {
    asm volatile(
        "mma.sync.aligned.m16n8k8.row.col.f32.tf32.tf32.f32 "
        "{%0,%1,%2,%3}, {%4,%5,%6,%7}, {%8,%9}, {%0,%1,%2,%3};"
        : "+f"(c[0]), "+f"(c[1]), "+f"(c[2]), "+f"(c[3])
        : "r"(a[0]), "r"(a[1]), "r"(a[2]), "r"(a[3]), "r"(b[0]), "r"(b[1]));
}

// swizzled float index inside the [128 px][128 col] staging buffer
__device__ __forceinline__ int stg_idx(int px, int col) {
    return px * 128 + (((col >> 2) ^ (px & 7)) << 2) + (col & 3);
}

// ---------------- prep kernels ----------------

// Per block: 64 pixels (mtile, wm half). Emits g_X rows + g_A fragment layout.
// g_A: [mtile(256)][chunk(8)] 16KB blocks; within: float4 at ((wi*4+kk)*32+lane)
//   element e of the float4 = A[r][c]: r = wi*16 + (lane>>2) + (e&1)*8 (wi = wm*4+i)
//   c = chunk*32 + kk*8 + (lane&3) + (e>>1)*4
__global__ void vq_prep(const float* __restrict__ z) {
    __shared__ float s[64 * 257];
    const int t = threadIdx.x;
    const int mtile = blockIdx.x >> 1, wm = blockIdx.x & 1;
    const int p0 = mtile * 128 + wm * 64;
    const int b = p0 >> 12, hw0 = p0 & 4095;
    const float* zb = z + (size_t)b * DD * HW + hw0;
#pragma unroll 8
    for (int i = 0; i < 64; i++) {
        int idx = i * 256 + t;
        int d = idx >> 6, px = idx & 63;
        s[px * 257 + d] = zb[(size_t)d * HW + px];
    }
    __syncthreads();
    // row-major copy
    float* gx = g_X + (size_t)p0 * DD;
#pragma unroll 8
    for (int i = 0; i < 64; i++)
        gx[(size_t)i * DD + t] = s[i * 257 + t];
    // fragment-packed copy
#pragma unroll
    for (int w = 0; w < 16; w++) {
        int pos = w * 256 + t;              // float4 position 0..4095
        int lane = pos & 31;
        int kk = (pos >> 5) & 3;
        int i = (pos >> 7) & 3;
        int c = pos >> 9;                   // chunk 0..7
        int rl = i * 16 + (lane >> 2);      // local row (0..63 half-relative? base row in half)
        int col = c * 32 + kk * 8 + (lane & 3);
        float4 v;
        v.x = s[rl * 257 + col];
        v.y = s[(rl + 8) * 257 + col];
        v.z = s[rl * 257 + col + 4];
        v.w = s[(rl + 8) * 257 + col + 4];
        float* dst = g_A + ((size_t)(mtile * 8 + c)) * 4096
                   + ((wm * 4 + i) * 4 + kk) * 128 + lane * 4;
        *(float4*)dst = v;
    }
}

// g_B: [ntile(64)][chunk(8)] 16KB blocks; float2 at ((wj*4+kk)*32+lane), wj = wn*4+j
//   element e: B[n][k]: n = wn*32 + j*8 + (lane>>2), k = chunk*32 + kk*8 + (lane&3) + e*4
__global__ void vq_packB(const float* __restrict__ cb) {
    const int t = threadIdx.x;
    const int nt = blockIdx.x >> 3, c = blockIdx.x & 7;
    const int k0 = nt * 128;
    float* dst = g_B + (size_t)blockIdx.x * 4096;
#pragma unroll
    for (int w = 0; w < 8; w++) {
        int pos = w * 256 + t;              // float2 position 0..2047
        int lane = pos & 31;
        int kk = (pos >> 5) & 3;
        int wj = pos >> 7;                  // 0..15
        int wn = wj >> 2, j = wj & 3;
        int rb = wn * 32 + j * 8 + (lane >> 2);
        int kc = c * 32 + kk * 8 + (lane & 3);
        const float* src = cb + (size_t)(k0 + rb) * DD + kc;
        float2 v = make_float2(src[0], src[4]);
        *(float2*)(dst + pos * 2) = v;
    }
}

__global__ void vq_xsq(const float* __restrict__ z) {
    int n = blockIdx.x * 256 + threadIdx.x;
    int b = n >> 12, hw = n & 4095;
    const float* p = z + (size_t)b * DD * HW + hw;
    float s = 0.f;
#pragma unroll 8
    for (int d = 0; d < DD; d++) {
        float v = p[(size_t)d * HW];
        s = fmaf(v, v, s);
    }
    g_xsq[n] = s;
}

__global__ void vq_cbsq(const float* __restrict__ cb) {
    int k = blockIdx.x * 256 + threadIdx.x;
    const float4* r = (const float4*)(cb + (size_t)k * DD);
    float s = 0.f;
#pragma unroll 8
    for (int i = 0; i < DD / 4; i++) {
        float4 v = r[i];
        s = fmaf(v.x, v.x, s); s = fmaf(v.y, v.y, s);
        s = fmaf(v.z, v.z, s); s = fmaf(v.w, v.w, s);
    }
    g_cbsq[k] = s;
}

// ---------------- tf32 mma.sync GEMM + logits + tile stats ----------------
// grid (256 m-tiles, 64 n-tiles), 256 threads (8 warps: 2 m x 4 n), 2 CTAs/SM
__global__ void __launch_bounds__(256, 2)
vq_gemm(const float* __restrict__ cb, float* __restrict__ out) {
    extern __shared__ float sm[];
    const int tid = threadIdx.x, lane = tid & 31, wid = tid >> 5;
    const int wm = wid & 1, wn = wid >> 1;
    const int mtile = blockIdx.x, ntile = blockIdx.y;
    const int n0 = mtile * 128, k0 = ntile * 128;
    const int b = n0 >> 12, hw0 = n0 & 4095;
    const uint32_t sb = smem_u32(sm);

    const float* gAb = g_A + (size_t)mtile * 8 * 4096;
    const float* gBb = g_B + (size_t)ntile * 8 * 4096;

    auto issue = [&](int c) {
        uint32_t base = sb + (uint32_t)(c % 3) * 32768u;
        const float* aS = gAb + (size_t)c * 4096;
        const float* bS = gBb + (size_t)c * 4096;
#pragma unroll
        for (int i = 0; i < 4; i++) {
            int p = tid + i * 256;
            cp16(base + p * 16, aS + p * 4);
        }
#pragma unroll
        for (int i = 0; i < 4; i++) {
            int p = tid + i * 256;
            cp16(base + 16384 + p * 16, bS + p * 4);
        }
        CP_COMMIT();
    };

    float acc[4][4][4];
#pragma unroll
    for (int i = 0; i < 4; i++)
#pragma unroll
        for (int j = 0; j < 4; j++)
#pragma unroll
            for (int r = 0; r < 4; r++) acc[i][j][r] = 0.f;

    issue(0); issue(1); issue(2);

#pragma unroll
    for (int c = 0; c < 8; c++) {
        if (c < 6)      { CP_WAIT2(); }
        else if (c == 6){ CP_WAIT1(); }
        else            { CP_WAIT0(); }
        __syncthreads();
        const float* As = sm + (c % 3) * 8192;
        const float* Bs = As + 4096;
#pragma unroll
        for (int kk = 0; kk < 4; kk++) {
            uint4 af[4]; uint2 bf[4];
#pragma unroll
            for (int i = 0; i < 4; i++)
                af[i] = *(const uint4*)(As + ((wm * 4 + i) * 4 + kk) * 128 + lane * 4);
#pragma unroll
            for (int j = 0; j < 4; j++)
                bf[j] = *(const uint2*)(Bs + ((wn * 4 + j) * 4 + kk) * 64 + lane * 2);
#pragma unroll
            for (int i = 0; i < 4; i++)
#pragma unroll
                for (int j = 0; j < 4; j++)
                    mma_tf32(acc[i][j], (const uint32_t*)&af[i], (const uint32_t*)&bf[j]);
        }
        __syncthreads();
        if (c + 3 < 8) issue(c + 3);
    }

    // phase 1: dump accumulators into smem staging [128 px][128 col] (swizzled)
#pragma unroll
    for (int i = 0; i < 4; i++) {
#pragma unroll
        for (int j = 0; j < 4; j++) {
            int px = wm * 64 + i * 16 + (lane >> 2);
            int col = wn * 32 + j * 8 + 2 * (lane & 3);
            *(float2*)&sm[stg_idx(px,     col)] = make_float2(acc[i][j][0], acc[i][j][1]);
            *(float2*)&sm[stg_idx(px + 8, col)] = make_float2(acc[i][j][2], acc[i][j][3]);
        }
    }
    __syncthreads();

    // phase 2: dist + coalesced logit stores + per-pixel min/argmin/second
    const int px = tid & 127, half = tid >> 7;
    const float xsv = g_xsq[n0 + px];
    float* lb = out + OFF_LOG + ((size_t)b * KK + k0) * HW + hw0 + px;
    float bv = __int_as_float(0x7f800000), sv = bv;
    int bk = 0;
#pragma unroll
    for (int it = 0; it < 16; it++) {
        int cg = half * 16 + it;        // float4 group of codes (0..31)
        float4 dv = *(const float4*)&sm[px * 128 + ((cg ^ (px & 7)) << 2)];
        float4 cq = *(const float4*)&g_cbsq[k0 + cg * 4];
        float d0 = fmaf(-2.f, dv.x, cq.x + xsv);
        float d1 = fmaf(-2.f, dv.y, cq.y + xsv);
        float d2 = fmaf(-2.f, dv.z, cq.z + xsv);
        float d3 = fmaf(-2.f, dv.w, cq.w + xsv);
        int kb = k0 + cg * 4;
        if (d0 < bv) { sv = bv; bv = d0; bk = kb;     } else if (d0 < sv) sv = d0;
        if (d1 < bv) { sv = bv; bv = d1; bk = kb + 1; } else if (d1 < sv) sv = d1;
        if (d2 < bv) { sv = bv; bv = d2; bk = kb + 2; } else if (d2 < sv) sv = d2;
        if (d3 < bv) { sv = bv; bv = d3; bk = kb + 3; } else if (d3 < sv) sv = d3;
        __stcs(lb + (size_t)(cg * 4 + 0) * HW, -d0);
        __stcs(lb + (size_t)(cg * 4 + 1) * HW, -d1);
        __stcs(lb + (size_t)(cg * 4 + 2) * HW, -d2);
        __stcs(lb + (size_t)(cg * 4 + 3) * HW, -d3);
    }
    float* fv = sm + 16384;
    int*   fk = (int*)(sm + 16640);
    float* f2 = sm + 16896;
    fv[tid] = bv; fk[tid] = bk; f2[tid] = sv;
    __syncthreads();
    if (tid < 128) {
        float v0 = fv[tid], v1 = fv[128 + tid];
        int   i0 = fk[tid], i1 = fk[128 + tid];
        float s0 = f2[tid], s1 = f2[128 + tid];
        float best; int bestk2;
        if (v1 < v0) { best = v1; bestk2 = i1; } else { best = v0; bestk2 = i0; }
        float other = (v1 < v0) ? v0 : v1;
        float second = fminf(other, fminf(s0, s1));
        size_t o = (size_t)ntile * NN + n0 + tid;
        g_pv[o] = best; g_pk[o] = bestk2; g_p2[o] = second;
    }
}

// ---------------- candidate rescore (exact fp32) + gather ----------------
__device__ __forceinline__ float exact_dist(const float* __restrict__ cb,
                                            int n, int k, float xsv) {
    const float4* xa = (const float4*)(g_X + (size_t)n * DD);
    const float4* cv = (const float4*)(cb + (size_t)k * DD);
    float s2 = 0.f;
#pragma unroll 8
    for (int q = 0; q < DD / 4; q++) {
        float4 a = xa[q]; float4 v = cv[q];
        s2 = fmaf(a.x, v.x, s2); s2 = fmaf(a.y, v.y, s2);
        s2 = fmaf(a.z, v.z, s2); s2 = fmaf(a.w, v.w, s2);
    }
    return fmaf(-2.f, s2, g_cbsq[k] + xsv);
}

// grid 128 blocks x 256 threads; thread owns one pixel
__global__ void __launch_bounds__(256)
vq_rescore(const float* __restrict__ cb, float* __restrict__ out) {
    const int t = threadIdx.x;
    const int n0 = blockIdx.x * 256;
    const int n = n0 + t;
    const int b = n >> 12, hw = n & 4095;
    const float xsv = g_xsq[n];

    // global tc-min over tiles
    float m = __int_as_float(0x7f800000);
#pragma unroll 8
    for (int s = 0; s < NTILES; s++) m = fminf(m, g_pv[(size_t)s * NN + n]);
    const float thresh = m + EPS;

    float bestv = __int_as_float(0x7f800000);
    int bestk = 0x7fffffff;
    const float* lg = out + OFF_LOG + (size_t)b * KK * HW + hw;

    for (int s = 0; s < NTILES; s++) {
        size_t o = (size_t)s * NN + n;
        float pv = g_pv[o];
        if (pv <= thresh) {
            int k = g_pk[o];
            float de = exact_dist(cb, n, k, xsv);
            if (de < bestv || (de == bestv && k < bestk)) { bestv = de; bestk = k; }
        }
        if (g_p2[o] <= thresh) {
            // rare fallback: sweep this tile's logits
            for (int j = 0; j < 128; j++) {
                int k = s * 128 + j;
                float dtc = -__ldcs(lg + (size_t)k * HW);
                if (dtc <= thresh) {
                    float de = exact_dist(cb, n, k, xsv);
                    if (de < bestv || (de == bestv && k < bestk)) { bestv = de; bestk = k; }
                }
            }
        }
    }

    // gather z_q for the winning code (coalesced across block per d)
    const float4* crow = (const float4*)(cb + (size_t)bestk * DD);
    size_t ob = (size_t)b * DD * HW + (n0 & 4095) + t;
#pragma unroll 8
    for (int q = 0; q < DD / 4; q++) {
        float4 v = crow[q];
        int d = q * 4;
        out[OFF_ZQ1 + ob + (size_t)(d + 0) * HW] = v.x;
        out[OFF_ZQ1 + ob + (size_t)(d + 1) * HW] = v.y;
        out[OFF_ZQ1 + ob + (size_t)(d + 2) * HW] = v.z;
        out[OFF_ZQ1 + ob + (size_t)(d + 3) * HW] = v.w;
        out[OFF_ZQ2 + ob + (size_t)(d + 0) * HW] = v.x;
        out[OFF_ZQ2 + ob + (size_t)(d + 1) * HW] = v.y;
        out[OFF_ZQ2 + ob + (size_t)(d + 2) * HW] = v.z;
        out[OFF_ZQ2 + ob + (size_t)(d + 3) * HW] = v.w;
    }
}

extern "C" void kernel_launch(void* const* d_in, const int* in_sizes, int n_in,
                              void* d_out, int out_size) {
    const float* z  = (const float*)d_in[0];
    const float* cb = (const float*)d_in[1];
    float* out = (float*)d_out;

    cudaFuncSetAttribute(vq_gemm, cudaFuncAttributeMaxDynamicSharedMemorySize, SMEM_BYTES);

    vq_prep<<<512, 256>>>(z);
    vq_packB<<<512, 256>>>(cb);
    vq_xsq<<<NN / 256, 256>>>(z);
    vq_cbsq<<<KK / 256, 256>>>(cb);
    vq_gemm<<<dim3(256, NTILES), 256, SMEM_BYTES>>>(cb, out);
    vq_rescore<<<NN / 256, 256>>>(cb, out);
}

// round 9
// speedup vs baseline: 9.1980x; 1.2935x over previous
#include <cuda_runtime.h>
#include <cstdint>

// Problem constants
#define DD   256
#define HW   4096
#define NN   32768
#define KK   8192
#define NTILES 64          // K tiles of 128 codes
#define EPS  2.5e-4f

// Scratch (no cudaMalloc allowed)
__device__ __align__(16) float g_A[(size_t)NN * DD];   // fragment-packed A (32 MB)
__device__ __align__(16) float g_B[(size_t)KK * DD];   // fragment-packed B (8 MB)
__device__ __align__(16) float g_X[(size_t)NN * DD];   // row-major pixels (32 MB)
__device__ __align__(16) float g_cbsq[KK];
__device__ float g_xsq[NN];
__device__ float g_pv[NTILES * NN];                    // per-(tile,pixel) tc-min
__device__ ulonglong2 g_mask[(size_t)NTILES * NN];     // 128-bit candidate masks (32 MB)

#define OFF_ZQ1 ((size_t)0)
#define OFF_ZQ2 ((size_t)NN * DD)
#define OFF_LOG ((size_t)2 * NN * DD)

#define SMEM_BYTES 98304    // 3 stages x 32KB; epilogue reuse: 64KB staging + reduce

// ---------------- helpers ----------------
__device__ __forceinline__ uint32_t smem_u32(const void* p) {
    uint32_t a;
    asm("{ .reg .u64 t; cvta.to.shared.u64 t, %1; cvt.u32.u64 %0, t; }" : "=r"(a) : "l"(p));
    return a;
}
__device__ __forceinline__ void cp16(uint32_t dst, const float* src) {
    asm volatile("cp.async.cg.shared.global [%0], [%1], 16;" :: "r"(dst), "l"(src));
}
#define CP_COMMIT() asm volatile("cp.async.commit_group;")
#define CP_WAIT2()  asm volatile("cp.async.wait_group 2;")
#define CP_WAIT1()  asm volatile("cp.async.wait_group 1;")
#define CP_WAIT0()  asm volatile("cp.async.wait_group 0;")

// tf32 mma: D = A(16x8 row) * B(8x8 col) + D
__device__ __forceinline__ void mma_tf32(float* c, const uint32_t* a, const uint32_t* b) {
    asm volatile(
        "mma.sync.aligned.m16n8k8.row.col.f32.tf32.tf32.f32 "
        "{%0,%1,%2,%3}, {%4,%5,%6,%7}, {%8,%9}, {%0,%1,%2,%3};"
        : "+f"(c[0]), "+f"(c[1]), "+f"(c[2]), "+f"(c[3])
        : "r"(a[0]), "r"(a[1]), "r"(a[2]), "r"(a[3]), "r"(b[0]), "r"(b[1]));
}

// swizzled float index inside the [128 px][128 col] staging buffer
__device__ __forceinline__ int stg_idx(int px, int col) {
    return px * 128 + (((col >> 2) ^ (px & 7)) << 2) + (col & 3);
}

// ---------------- prep kernels ----------------

// Per block: 64 pixels. Emits g_X rows + g_A fragment layout + g_xsq.
__global__ void vq_prep(const float* __restrict__ z) {
    __shared__ float s[64 * 257];
    __shared__ float ps[256];
    const int t = threadIdx.x;
    const int mtile = blockIdx.x >> 1, wm = blockIdx.x & 1;
    const int p0 = mtile * 128 + wm * 64;
    const int b = p0 >> 12, hw0 = p0 & 4095;
    const float* zb = z + (size_t)b * DD * HW + hw0;
#pragma unroll 8
    for (int i = 0; i < 64; i++) {
        int idx = i * 256 + t;
        int d = idx >> 6, px = idx & 63;
        s[px * 257 + d] = zb[(size_t)d * HW + px];
    }
    __syncthreads();
    // xsq: 4-way split per pixel (uniform per-pixel shift -> argmin-safe)
    {
        int p = t >> 2, q = t & 3;
        const float* row = s + p * 257 + q * 64;
        float acc = 0.f;
#pragma unroll 8
        for (int i = 0; i < 64; i++) acc = fmaf(row[i], row[i], acc);
        ps[t] = acc;
    }
    // row-major copy
    float* gx = g_X + (size_t)p0 * DD;
#pragma unroll 8
    for (int i = 0; i < 64; i++)
        gx[(size_t)i * DD + t] = s[i * 257 + t];
    // fragment-packed copy
#pragma unroll
    for (int w = 0; w < 16; w++) {
        int pos = w * 256 + t;              // float4 position 0..4095
        int lane = pos & 31;
        int kk = (pos >> 5) & 3;
        int i = (pos >> 7) & 3;
        int c = pos >> 9;                   // chunk 0..7
        int rl = i * 16 + (lane >> 2);
        int col = c * 32 + kk * 8 + (lane & 3);
        float4 v;
        v.x = s[rl * 257 + col];
        v.y = s[(rl + 8) * 257 + col];
        v.z = s[rl * 257 + col + 4];
        v.w = s[(rl + 8) * 257 + col + 4];
        float* dst = g_A + ((size_t)(mtile * 8 + c)) * 4096
                   + ((wm * 4 + i) * 4 + kk) * 128 + lane * 4;
        *(float4*)dst = v;
    }
    __syncthreads();
    if (t < 64)
        g_xsq[p0 + t] = ((ps[t * 4] + ps[t * 4 + 1]) + ps[t * 4 + 2]) + ps[t * 4 + 3];
}

// g_B: [ntile(64)][chunk(8)] 16KB blocks; float2 at ((wj*4+kk)*32+lane), wj = wn*4+j
__global__ void vq_packB(const float* __restrict__ cb) {
    const int t = threadIdx.x;
    const int nt = blockIdx.x >> 3, c = blockIdx.x & 7;
    const int k0 = nt * 128;
    float* dst = g_B + (size_t)blockIdx.x * 4096;
#pragma unroll
    for (int w = 0; w < 8; w++) {
        int pos = w * 256 + t;
        int lane = pos & 31;
        int kk = (pos >> 5) & 3;
        int wj = pos >> 7;
        int wn = wj >> 2, j = wj & 3;
        int rb = wn * 32 + j * 8 + (lane >> 2);
        int kc = c * 32 + kk * 8 + (lane & 3);
        const float* src = cb + (size_t)(k0 + rb) * DD + kc;
        *(float2*)(dst + pos * 2) = make_float2(src[0], src[4]);
    }
}

// warp-per-code ||c||^2 (shfl-reduce order: cbsq shift ~1e-13, negligible)
__global__ void vq_cbsq(const float* __restrict__ cb) {
    int w = (blockIdx.x * 256 + threadIdx.x) >> 5;
    int lane = threadIdx.x & 31;
    const float* r = cb + (size_t)w * DD + lane;
    float s = 0.f;
#pragma unroll
    for (int i = 0; i < 8; i++) { float v = r[i * 32]; s = fmaf(v, v, s); }
#pragma unroll
    for (int o = 16; o > 0; o >>= 1)
        s += __shfl_xor_sync(0xffffffffu, s, o);
    if (lane == 0) g_cbsq[w] = s;
}

// ---------------- tf32 mma.sync GEMM + logits + tile min/mask ----------------
// grid (256 m-tiles, 64 n-tiles), 256 threads (8 warps: 2 m x 4 n), 2 CTAs/SM
__global__ void __launch_bounds__(256, 2)
vq_gemm(const float* __restrict__ cb, float* __restrict__ out) {
    extern __shared__ float sm[];
    const int tid = threadIdx.x, lane = tid & 31, wid = tid >> 5;
    const int wm = wid & 1, wn = wid >> 1;
    const int mtile = blockIdx.x, ntile = blockIdx.y;
    const int n0 = mtile * 128, k0 = ntile * 128;
    const int b = n0 >> 12, hw0 = n0 & 4095;
    const uint32_t sb = smem_u32(sm);

    const float* gAb = g_A + (size_t)mtile * 8 * 4096;
    const float* gBb = g_B + (size_t)ntile * 8 * 4096;

    auto issue = [&](int c) {
        uint32_t base = sb + (uint32_t)(c % 3) * 32768u;
        const float* aS = gAb + (size_t)c * 4096;
        const float* bS = gBb + (size_t)c * 4096;
#pragma unroll
        for (int i = 0; i < 4; i++) { int p = tid + i * 256; cp16(base + p * 16, aS + p * 4); }
#pragma unroll
        for (int i = 0; i < 4; i++) { int p = tid + i * 256; cp16(base + 16384 + p * 16, bS + p * 4); }
        CP_COMMIT();
    };

    float acc[4][4][4];
#pragma unroll
    for (int i = 0; i < 4; i++)
#pragma unroll
        for (int j = 0; j < 4; j++)
#pragma unroll
            for (int r = 0; r < 4; r++) acc[i][j][r] = 0.f;

    issue(0); issue(1); issue(2);

#pragma unroll
    for (int c = 0; c < 8; c++) {
        if (c < 6)      { CP_WAIT2(); }
        else if (c == 6){ CP_WAIT1(); }
        else            { CP_WAIT0(); }
        __syncthreads();
        const float* As = sm + (c % 3) * 8192;
        const float* Bs = As + 4096;
#pragma unroll
        for (int kk = 0; kk < 4; kk++) {
            uint4 af[4]; uint2 bf[4];
#pragma unroll
            for (int i = 0; i < 4; i++)
                af[i] = *(const uint4*)(As + ((wm * 4 + i) * 4 + kk) * 128 + lane * 4);
#pragma unroll
            for (int j = 0; j < 4; j++)
                bf[j] = *(const uint2*)(Bs + ((wn * 4 + j) * 4 + kk) * 64 + lane * 2);
#pragma unroll
            for (int i = 0; i < 4; i++)
#pragma unroll
                for (int j = 0; j < 4; j++)
                    mma_tf32(acc[i][j], (const uint32_t*)&af[i], (const uint32_t*)&bf[j]);
        }
        __syncthreads();
        if (c + 3 < 8) issue(c + 3);
    }

    // phase 1: dump accumulators into smem staging [128 px][128 col] (swizzled)
#pragma unroll
    for (int i = 0; i < 4; i++) {
#pragma unroll
        for (int j = 0; j < 4; j++) {
            int px = wm * 64 + i * 16 + (lane >> 2);
            int col = wn * 32 + j * 8 + 2 * (lane & 3);
            *(float2*)&sm[stg_idx(px,     col)] = make_float2(acc[i][j][0], acc[i][j][1]);
            *(float2*)&sm[stg_idx(px + 8, col)] = make_float2(acc[i][j][2], acc[i][j][3]);
        }
    }
    __syncthreads();

    // phase 2: dist + coalesced logit stores + per-pixel min
    const int px = tid & 127, half = tid >> 7;
    const float xsv = g_xsq[n0 + px];
    float* lb = out + OFF_LOG + ((size_t)b * KK + k0) * HW + hw0 + px;
    float bv = __int_as_float(0x7f800000);
#pragma unroll
    for (int it = 0; it < 16; it++) {
        int cg = half * 16 + it;
        float4 dv = *(const float4*)&sm[px * 128 + ((cg ^ (px & 7)) << 2)];
        float4 cq = *(const float4*)&g_cbsq[k0 + cg * 4];
        float d0 = fmaf(-2.f, dv.x, cq.x + xsv);
        float d1 = fmaf(-2.f, dv.y, cq.y + xsv);
        float d2 = fmaf(-2.f, dv.z, cq.z + xsv);
        float d3 = fmaf(-2.f, dv.w, cq.w + xsv);
        bv = fminf(bv, fminf(fminf(d0, d1), fminf(d2, d3)));
        __stcs(lb + (size_t)(cg * 4 + 0) * HW, -d0);
        __stcs(lb + (size_t)(cg * 4 + 1) * HW, -d1);
        __stcs(lb + (size_t)(cg * 4 + 2) * HW, -d2);
        __stcs(lb + (size_t)(cg * 4 + 3) * HW, -d3);
    }
    float* fv  = sm + 16384;   // [256]
    float* pvw = sm + 16640;   // [128] combined per-pixel min
    fv[tid] = bv;
    __syncthreads();
    if (tid < 128) {
        float comb = fminf(fv[tid], fv[128 + tid]);
        g_pv[(size_t)ntile * NN + n0 + tid] = comb;
        pvw[tid] = comb;
    }
    __syncthreads();

    // phase 3: candidate bitmask (codes with dtc <= tile_min + EPS)
    const float thr = pvw[px] + EPS;
    unsigned long long m64 = 0;
#pragma unroll
    for (int it = 0; it < 16; it++) {
        int cg = half * 16 + it;
        float4 dv = *(const float4*)&sm[px * 128 + ((cg ^ (px & 7)) << 2)];
        float4 cq = *(const float4*)&g_cbsq[k0 + cg * 4];
        float d0 = fmaf(-2.f, dv.x, cq.x + xsv);
        float d1 = fmaf(-2.f, dv.y, cq.y + xsv);
        float d2 = fmaf(-2.f, dv.z, cq.z + xsv);
        float d3 = fmaf(-2.f, dv.w, cq.w + xsv);
        if (d0 <= thr) m64 |= 1ull << (it * 4 + 0);
        if (d1 <= thr) m64 |= 1ull << (it * 4 + 1);
        if (d2 <= thr) m64 |= 1ull << (it * 4 + 2);
        if (d3 <= thr) m64 |= 1ull << (it * 4 + 3);
    }
    ((unsigned long long*)g_mask)[((size_t)ntile * NN + n0 + px) * 2 + half] = m64;
}

// ---------------- exact rescore of masked candidates + gather ----------------
// grid 512 blocks x 256 threads; block owns 64 pixels (X rows cached in smem)
__global__ void __launch_bounds__(256)
vq_rescore(const float* __restrict__ cb, float* __restrict__ out) {
    __shared__ float Xs[64 * 260];
    __shared__ int sidx[64];
    const int t = threadIdx.x;
    const int n0 = blockIdx.x * 64;
    const int b = n0 >> 12, hw0 = n0 & 4095;

    const float4* gx = (const float4*)(g_X + (size_t)n0 * DD);
#pragma unroll
    for (int i = 0; i < 16; i++) {
        int idx = t + i * 256;
        int px = idx >> 6, q = idx & 63;
        *(float4*)&Xs[px * 260 + q * 4] = gx[px * 64 + q];
    }
    __syncthreads();

    if (t < 64) {
        const int n = n0 + t;
        const float xsv = g_xsq[n];
        float m = __int_as_float(0x7f800000);
#pragma unroll 8
        for (int s = 0; s < NTILES; s++) m = fminf(m, g_pv[(size_t)s * NN + n]);
        const float thresh = m + EPS;

        float bestv = __int_as_float(0x7f800000);
        int bestk = 0x7fffffff;
        const float* xr = &Xs[t * 260];

        for (int s = 0; s < NTILES; s++) {
            if (g_pv[(size_t)s * NN + n] <= thresh) {
                ulonglong2 mk = g_mask[(size_t)s * NN + n];
#pragma unroll
                for (int w = 0; w < 2; w++) {
                    unsigned long long mw = w ? mk.y : mk.x;
                    while (mw) {
                        int j = __ffsll(mw) - 1;
                        mw &= mw - 1;
                        int k = s * 128 + w * 64 + j;
                        const float4* cv = (const float4*)(cb + (size_t)k * DD);
                        float s2 = 0.f;
#pragma unroll 8
                        for (int q = 0; q < 64; q++) {
                            float4 a = *(const float4*)&xr[q * 4];
                            float4 v = cv[q];
                            s2 = fmaf(a.x, v.x, s2); s2 = fmaf(a.y, v.y, s2);
                            s2 = fmaf(a.z, v.z, s2); s2 = fmaf(a.w, v.w, s2);
                        }
                        float de = fmaf(-2.f, s2, g_cbsq[k] + xsv);
                        if (de < bestv || (de == bestv && k < bestk)) { bestv = de; bestk = k; }
                    }
                }
            }
        }
        sidx[t] = bestk;
    }
    __syncthreads();

    // gather z_q (both copies)
    const int px = t & 63, dg = t >> 6;
    const float* crow = cb + (size_t)sidx[px] * DD;
    size_t ob = (size_t)b * DD * HW + hw0 + px;
#pragma unroll 8
    for (int dj = 0; dj < 64; dj++) {
        int d = dg * 64 + dj;
        float v = crow[d];
        out[OFF_ZQ1 + ob + (size_t)d * HW] = v;
        out[OFF_ZQ2 + ob + (size_t)d * HW] = v;
    }
}

extern "C" void kernel_launch(void* const* d_in, const int* in_sizes, int n_in,
                              void* d_out, int out_size) {
    const float* z  = (const float*)d_in[0];
    const float* cb = (const float*)d_in[1];
    float* out = (float*)d_out;

    cudaFuncSetAttribute(vq_gemm, cudaFuncAttributeMaxDynamicSharedMemorySize, SMEM_BYTES);

    vq_prep<<<512, 256>>>(z);
    vq_packB<<<512, 256>>>(cb);
    vq_cbsq<<<KK / 8 / 8, 256>>>(cb);   // 8 codes per block (warp per code)
    vq_gemm<<<dim3(256, NTILES), 256, SMEM_BYTES>>>(cb, out);
    vq_rescore<<<NN / 64, 256>>>(cb, out);
}